// round 1
// baseline (speedup 1.0000x reference)
#include <cuda_runtime.h>

#define NK 48          // knots per dim
#define NP 50          // padded grid extent (NK + 2)
#define NV 16          // output channels
#define ND 3

// 8 MB padded grid: [NP][NP][NP][NV], linear-extrapolation padded on all axes.
__device__ float g_pad[NP * NP * NP * NV];

// Per-axis padding taps: padded index p -> up to 2 (source, coeff) pairs.
__device__ __forceinline__ void pad_taps(int p, int* s, float* c) {
    if (p == 0)            { s[0] = 0;      c[0] = 2.f; s[1] = 1;      c[1] = -1.f; }
    else if (p == NK + 1)  { s[0] = NK - 1; c[0] = 2.f; s[1] = NK - 2; c[1] = -1.f; }
    else                   { s[0] = p - 1;  c[0] = 1.f; s[1] = 0;      c[1] = 0.f;  }
}

__global__ void pad_grid_kernel(const float* __restrict__ grid) {
    int t = blockIdx.x * blockDim.x + threadIdx.x;
    const int total = NP * NP * NP * NV;
    if (t >= total) return;
    int v = t & (NV - 1);
    int r = t >> 4;          // NV == 16
    int k = r % NP; r /= NP;
    int j = r % NP;
    int i = r / NP;

    int si[2], sj[2], sk[2];
    float ci[2], cj[2], ck[2];
    pad_taps(i, si, ci);
    pad_taps(j, sj, cj);
    pad_taps(k, sk, ck);

    float acc = 0.f;
    #pragma unroll
    for (int a = 0; a < 2; a++) {
        if (ci[a] == 0.f) continue;
        #pragma unroll
        for (int b = 0; b < 2; b++) {
            if (cj[b] == 0.f) continue;
            #pragma unroll
            for (int e = 0; e < 2; e++) {
                if (ck[e] == 0.f) continue;
                acc += ci[a] * cj[b] * ck[e] *
                       grid[((si[a] * NK + sj[b]) * NK + sk[e]) * NV + v];
            }
        }
    }
    g_pad[t] = acc;
}

// 4 threads per point; thread (p, c) accumulates channels [4c, 4c+4).
__global__ void catmullrom_kernel(const float* __restrict__ x,
                                  const float* __restrict__ knots,
                                  float* __restrict__ out, int B) {
    __shared__ float sk[ND * NK];
    for (int i = threadIdx.x; i < ND * NK; i += blockDim.x) sk[i] = knots[i];
    __syncthreads();

    int t = blockIdx.x * blockDim.x + threadIdx.x;
    int p = t >> 2;
    int c = t & 3;
    if (p >= B) return;

    float w[ND][4];
    int base[ND];

    #pragma unroll
    for (int d = 0; d < ND; d++) {
        const float* kd = sk + d * NK;
        float xd = x[p * 3 + d];
        // searchsorted(kd, xd, side='right') - 1, clipped to [0, NK-2]
        int lo = 0, hi = NK;
        while (lo < hi) {
            int m = (lo + hi) >> 1;
            if (kd[m] <= xd) lo = m + 1; else hi = m;
        }
        int idx = min(max(lo - 1, 0), NK - 2);

        float t0 = kd[idx], t1 = kd[idx + 1];
        float dt = t1 - t0;
        float u  = (xd - t0) / dt;
        float u2 = u * u, u3 = u2 * u;
        float h00 =  2.f * u3 - 3.f * u2 + 1.f;
        float h10 =        u3 - 2.f * u2 + u;
        float h01 = -2.f * u3 + 3.f * u2;
        float h11 =        u3 -       u2;

        // tp[idx]   = kd[idx-1] (or 2k0-k1),  tp[idx+2] = kd[idx+1]
        // tp[idx+1] = kd[idx],  tp[idx+3] = kd[idx+2] (or 2k[N-1]-k[N-2])
        float tm1 = (idx >= 1)      ? kd[idx - 1] : 2.f * kd[0] - kd[1];
        float tp2 = (idx + 2 < NK)  ? kd[idx + 2] : 2.f * kd[NK - 1] - kd[NK - 2];
        float a = dt / (t1 - tm1);
        float b = dt / (tp2 - t0);

        w[d][0] = -h10 * a;
        w[d][1] = h00 - h11 * b;
        w[d][2] = h01 + h10 * a;
        w[d][3] = h11 * b;
        base[d] = idx;
    }

    const float4* gp = (const float4*)g_pad;
    float4 acc = make_float4(0.f, 0.f, 0.f, 0.f);

    #pragma unroll
    for (int i = 0; i < 4; i++) {
        #pragma unroll
        for (int j = 0; j < 4; j++) {
            float wij = w[0][i] * w[1][j];
            int off = (((base[0] + i) * NP + (base[1] + j)) * NP + base[2]) * (NV / 4) + c;
            #pragma unroll
            for (int k = 0; k < 4; k++) {
                float4 g = __ldg(gp + off + k * (NV / 4));
                float ww = wij * w[2][k];
                acc.x = fmaf(ww, g.x, acc.x);
                acc.y = fmaf(ww, g.y, acc.y);
                acc.z = fmaf(ww, g.z, acc.z);
                acc.w = fmaf(ww, g.w, acc.w);
            }
        }
    }

    ((float4*)out)[p * 4 + c] = acc;
}

extern "C" void kernel_launch(void* const* d_in, const int* in_sizes, int n_in,
                              void* d_out, int out_size) {
    const float* x     = (const float*)d_in[0];
    const float* knots = (const float*)d_in[1];
    const float* grid  = (const float*)d_in[2];
    float* out = (float*)d_out;

    int B = in_sizes[0] / 3;

    const int padTotal = NP * NP * NP * NV;
    pad_grid_kernel<<<(padTotal + 255) / 256, 256>>>(grid);

    int threads = B * 4;
    catmullrom_kernel<<<(threads + 255) / 256, 256>>>(x, knots, out, B);
}

// round 2
// speedup vs baseline: 1.1932x; 1.1932x over previous
#include <cuda_runtime.h>

#define NK 48          // knots per dim
#define NP 50          // padded grid extent (NK + 2)
#define NV 16          // output channels
#define ND 3

// 8 MB padded grid: [NP][NP][NP][NV], linear-extrapolation padded on all axes.
__device__ float g_pad[NP * NP * NP * NV];

// Per-axis padding taps: padded index p -> up to 2 (source, coeff) pairs.
__device__ __forceinline__ void pad_taps(int p, int* s, float* c) {
    if (p == 0)            { s[0] = 0;      c[0] = 2.f; s[1] = 1;      c[1] = -1.f; }
    else if (p == NK + 1)  { s[0] = NK - 1; c[0] = 2.f; s[1] = NK - 2; c[1] = -1.f; }
    else                   { s[0] = p - 1;  c[0] = 1.f; s[1] = 0;      c[1] = 0.f;  }
}

// float4-vectorized pad: one thread per float4 (4 channels) of the padded grid.
__global__ void pad_grid_kernel(const float* __restrict__ grid) {
    int t = blockIdx.x * blockDim.x + threadIdx.x;
    const int total = NP * NP * NP * 4;
    if (t >= total) return;
    int c = t & 3;
    int r = t >> 2;
    int k = r % NP; r /= NP;
    int j = r % NP;
    int i = r / NP;

    const float4* g4 = (const float4*)grid;
    float4* o4 = (float4*)g_pad;

    if (i >= 1 && i <= NK && j >= 1 && j <= NK && k >= 1 && k <= NK) {
        // interior: straight copy
        o4[t] = __ldg(g4 + (((i - 1) * NK + (j - 1)) * NK + (k - 1)) * 4 + c);
        return;
    }

    int si[2], sj[2], sk_[2];
    float ci[2], cj[2], ck[2];
    pad_taps(i, si, ci);
    pad_taps(j, sj, cj);
    pad_taps(k, sk_, ck);

    float4 acc = make_float4(0.f, 0.f, 0.f, 0.f);
    #pragma unroll
    for (int a = 0; a < 2; a++) {
        if (ci[a] == 0.f) continue;
        #pragma unroll
        for (int b = 0; b < 2; b++) {
            if (cj[b] == 0.f) continue;
            #pragma unroll
            for (int e = 0; e < 2; e++) {
                if (ck[e] == 0.f) continue;
                float w = ci[a] * cj[b] * ck[e];
                float4 g = __ldg(g4 + ((si[a] * NK + sj[b]) * NK + sk_[e]) * 4 + c);
                acc.x = fmaf(w, g.x, acc.x);
                acc.y = fmaf(w, g.y, acc.y);
                acc.z = fmaf(w, g.z, acc.z);
                acc.w = fmaf(w, g.w, acc.w);
            }
        }
    }
    o4[t] = acc;
}

// 16 lanes per point (2 points per warp). Lane l = lane&15: k = l>>2, c = l&3.
// For each (i,j), the 16 lanes load one contiguous 256B k-row via LDG.128.
// Lanes l<3 compute the per-dim weights; shuffles broadcast to the group.
// k-reduction via shfl_xor(4), shfl_xor(8); lanes k==0 store float4.
__global__ void catmullrom_kernel(const float* __restrict__ x,
                                  const float* __restrict__ knots,
                                  float* __restrict__ out, int B) {
    __shared__ float sk[ND * NK];
    for (int i = threadIdx.x; i < ND * NK; i += blockDim.x) sk[i] = knots[i];
    __syncthreads();

    const unsigned m = 0xffffffffu;
    int gtid = blockIdx.x * blockDim.x + threadIdx.x;
    int warp = gtid >> 5;
    int lane = threadIdx.x & 31;
    int half = lane >> 4;     // which point within the warp
    int l    = lane & 15;     // lane within the point group
    int k    = l >> 2;
    int c    = l & 3;
    int p    = warp * 2 + half;
    if (p >= B) return;       // B even -> whole warp exits together

    // --- per-dim weights (lanes l<3 only; dim d == l) ---
    float wl0 = 0.f, wl1 = 0.f, wl2 = 0.f, wl3 = 0.f;
    int basel = 0;
    if (l < ND) {
        const float* kd = sk + l * NK;
        float xd = x[p * 3 + l];
        int lo = 0, hi = NK;
        while (lo < hi) {
            int mid = (lo + hi) >> 1;
            if (kd[mid] <= xd) lo = mid + 1; else hi = mid;
        }
        int idx = min(max(lo - 1, 0), NK - 2);

        float t0 = kd[idx], t1 = kd[idx + 1];
        float dt = t1 - t0;
        float u  = (xd - t0) / dt;
        float u2 = u * u, u3 = u2 * u;
        float h00 =  2.f * u3 - 3.f * u2 + 1.f;
        float h10 =        u3 - 2.f * u2 + u;
        float h01 = -2.f * u3 + 3.f * u2;
        float h11 =        u3 -       u2;

        float tm1 = (idx >= 1)     ? kd[idx - 1] : 2.f * kd[0] - kd[1];
        float tp2 = (idx + 2 < NK) ? kd[idx + 2] : 2.f * kd[NK - 1] - kd[NK - 2];
        float a = dt / (t1 - tm1);
        float b = dt / (tp2 - t0);

        wl0 = -h10 * a;
        wl1 = h00 - h11 * b;
        wl2 = h01 + h10 * a;
        wl3 = h11 * b;
        basel = idx;
    }

    // --- broadcast weights/bases from lanes (half*16 + d) ---
    int s0 = (half << 4);
    float w0[4], w1[4], w2v[4];
    w0[0]  = __shfl_sync(m, wl0, s0 + 0);
    w0[1]  = __shfl_sync(m, wl1, s0 + 0);
    w0[2]  = __shfl_sync(m, wl2, s0 + 0);
    w0[3]  = __shfl_sync(m, wl3, s0 + 0);
    w1[0]  = __shfl_sync(m, wl0, s0 + 1);
    w1[1]  = __shfl_sync(m, wl1, s0 + 1);
    w1[2]  = __shfl_sync(m, wl2, s0 + 1);
    w1[3]  = __shfl_sync(m, wl3, s0 + 1);
    w2v[0] = __shfl_sync(m, wl0, s0 + 2);
    w2v[1] = __shfl_sync(m, wl1, s0 + 2);
    w2v[2] = __shfl_sync(m, wl2, s0 + 2);
    w2v[3] = __shfl_sync(m, wl3, s0 + 2);
    int b0 = __shfl_sync(m, basel, s0 + 0);
    int b1 = __shfl_sync(m, basel, s0 + 1);
    int b2 = __shfl_sync(m, basel, s0 + 2);

    float wc = (k == 0) ? w2v[0] : (k == 1) ? w2v[1] : (k == 2) ? w2v[2] : w2v[3];

    // --- gather: 16 (i,j) rows, each a contiguous 256B load across the group ---
    const float4* gp = (const float4*)g_pad;
    int off00 = ((b0 * NP + b1) * NP + b2 + k) * 4 + c;  // float4 index for (i=0,j=0)
    float4 acc = make_float4(0.f, 0.f, 0.f, 0.f);

    #pragma unroll
    for (int i = 0; i < 4; i++) {
        #pragma unroll
        for (int j = 0; j < 4; j++) {
            float w = w0[i] * w1[j] * wc;
            float4 g = __ldg(gp + off00 + (i * NP + j) * (NP * 4));
            acc.x = fmaf(w, g.x, acc.x);
            acc.y = fmaf(w, g.y, acc.y);
            acc.z = fmaf(w, g.z, acc.z);
            acc.w = fmaf(w, g.w, acc.w);
        }
    }

    // --- reduce over k (lane bits 2,3) ---
    #pragma unroll
    for (int s = 4; s <= 8; s <<= 1) {
        acc.x += __shfl_xor_sync(m, acc.x, s);
        acc.y += __shfl_xor_sync(m, acc.y, s);
        acc.z += __shfl_xor_sync(m, acc.z, s);
        acc.w += __shfl_xor_sync(m, acc.w, s);
    }

    if (k == 0) {
        ((float4*)out)[p * 4 + c] = acc;
    }
}

extern "C" void kernel_launch(void* const* d_in, const int* in_sizes, int n_in,
                              void* d_out, int out_size) {
    const float* x     = (const float*)d_in[0];
    const float* knots = (const float*)d_in[1];
    const float* grid  = (const float*)d_in[2];
    float* out = (float*)d_out;

    int B = in_sizes[0] / 3;

    const int padTotal = NP * NP * NP * 4;
    pad_grid_kernel<<<(padTotal + 255) / 256, 256>>>(grid);

    long long threads = (long long)B * 16;
    catmullrom_kernel<<<(int)((threads + 255) / 256), 256>>>(x, knots, out, B);
}